// round 5
// baseline (speedup 1.0000x reference)
#include <cuda_runtime.h>
#include <math.h>

#define T_SEQ 700
#define BATCH 32
#define HID 800
#define DIN 53
#define G4 3200       // 4*HID
#define L1K 1600      // 2*HID
#define NA 60
#define RNNOUT 1653   // 2*HID + DIN
#define NB_LSTM 148
#define LSTM_SMEM ((HID*BATCH + 44*BATCH + 11*BATCH) * 4)

// ---------------- scratch (static device allocations) ----------------
__device__ float g_xT  [(size_t)T_SEQ*DIN*BATCH];      // x transposed  [t][53][32]
__device__ float g_cbuf[(size_t)T_SEQ*BATCH*G4];       // GEMM output   [t*32+b][3200]
__device__ float g_xgTf[(size_t)T_SEQ*G4*BATCH];       // xg fwd        [t][3200][32]
__device__ float g_xgTb[(size_t)T_SEQ*G4*BATCH];       // xg bwd        [t][3200][32]
__device__ float g_h0T [(size_t)T_SEQ*L1K*BATCH];      // layer0 out    [t][1600][32]
__device__ float g_h1T [(size_t)T_SEQ*L1K*BATCH];      // layer1 out    [t][1600][32]
__device__ float g_hstate[2*2*HID*BATCH];              // [dir][parity][800][32]
__device__ float g_dih [T_SEQ*BATCH*3];
__device__ unsigned g_bar_cnt;
__device__ volatile unsigned g_bar_gen;

// ---------------- build x (embedding + evolutionary concat), TKB layout ----
__global__ __launch_bounds__(256) void build_x_kernel(
        const int* __restrict__ primary,
        const float* __restrict__ evo,
        const float* __restrict__ emb) {
    int t = blockIdx.x;
    for (int idx = threadIdx.x; idx < DIN*BATCH; idx += 256) {
        int d = idx >> 5;
        int b = idx & 31;
        float v;
        if (d < 32) {
            int p = primary[t*BATCH + b];
            v = emb[p*32 + d];
        } else {
            v = evo[((size_t)t*BATCH + b)*21 + (d - 32)];
        }
        g_xT[((size_t)t*DIN + d)*BATCH + b] = v;
    }
}

// ---------------- fp32 SGEMM: cbuf[M][3200] = A_tkb @ B^T + bias ------------
// A in TKB layout [T][K][32] (logical row m = t*32+b), B row-major [3200][K]
__global__ __launch_bounds__(256) void gemm_tkb_kernel(
        const float* __restrict__ Bm, const float* __restrict__ bias,
        int K, int a_sel) {
    const float* __restrict__ A = a_sel ? g_h0T : g_xT;
    __shared__ float As[8][128];
    __shared__ float Bs[8][128];
    int m0 = blockIdx.x * 128;
    int n0 = blockIdx.y * 128;
    int tid = threadIdx.x;
    int tx = tid & 15, ty = tid >> 4;

    float acc[8][8];
    #pragma unroll
    for (int i = 0; i < 8; i++)
        #pragma unroll
        for (int j = 0; j < 8; j++) acc[i][j] = 0.f;

    int klA = tid >> 5;   // 0..7
    int blA = tid & 31;
    int klB = tid & 7;    // 0..7
    int nlB = tid >> 3;   // 0..31

    for (int k0 = 0; k0 < K; k0 += 8) {
        #pragma unroll
        for (int i = 0; i < 4; i++) {
            int m = m0 + blA + i*32;
            int k = k0 + klA;
            int tt = m >> 5, bb = m & 31;
            As[klA][blA + i*32] = (k < K) ? A[((size_t)tt*K + k)*BATCH + bb] : 0.f;
        }
        #pragma unroll
        for (int i = 0; i < 4; i++) {
            int n = n0 + nlB + i*32;
            int k = k0 + klB;
            Bs[klB][nlB + i*32] = (k < K) ? Bm[(size_t)n*K + k] : 0.f;
        }
        __syncthreads();
        #pragma unroll
        for (int kk = 0; kk < 8; kk++) {
            float4 a0 = *(const float4*)&As[kk][ty*8];
            float4 a1 = *(const float4*)&As[kk][ty*8+4];
            float4 b0 = *(const float4*)&Bs[kk][tx*8];
            float4 b1 = *(const float4*)&Bs[kk][tx*8+4];
            float av[8] = {a0.x,a0.y,a0.z,a0.w,a1.x,a1.y,a1.z,a1.w};
            float bv[8] = {b0.x,b0.y,b0.z,b0.w,b1.x,b1.y,b1.z,b1.w};
            #pragma unroll
            for (int i = 0; i < 8; i++)
                #pragma unroll
                for (int j = 0; j < 8; j++)
                    acc[i][j] = fmaf(av[i], bv[j], acc[i][j]);
        }
        __syncthreads();
    }
    #pragma unroll
    for (int i = 0; i < 8; i++) {
        int row = m0 + ty*8 + i;
        #pragma unroll
        for (int j = 0; j < 8; j++) {
            int col = n0 + tx*8 + j;
            g_cbuf[(size_t)row*G4 + col] = acc[i][j] + bias[col];
        }
    }
}

// ---------------- transpose g_cbuf [t*32+b][3200] -> xgT [t][3200][32] ------
__global__ void transpose_kernel(int dst_sel) {
    float* __restrict__ dst = dst_sel ? g_xgTb : g_xgTf;
    __shared__ float sm[32][33];
    int t  = blockIdx.x;
    int n0 = blockIdx.y * 32;
    int x = threadIdx.x, y = threadIdx.y;   // 32 x 8
    #pragma unroll
    for (int i = 0; i < 4; i++) {
        int b = y + i*8;
        sm[b][x] = g_cbuf[((size_t)t*BATCH + b)*G4 + n0 + x];
    }
    __syncthreads();
    #pragma unroll
    for (int i = 0; i < 4; i++) {
        int n = y + i*8;
        dst[((size_t)t*G4 + n0 + n)*BATCH + x] = sm[x][n];
    }
}

// ---------------- device-wide barrier (generation based) --------------------
__device__ __forceinline__ void grid_barrier() {
    __syncthreads();
    if (threadIdx.x == 0) {
        unsigned my = g_bar_gen;
        __threadfence();
        if (atomicAdd(&g_bar_cnt, 1) == NB_LSTM - 1) {
            g_bar_cnt = 0;
            __threadfence();
            g_bar_gen = my + 1;
        } else {
            while (g_bar_gen == my) { }
            __threadfence();
        }
    }
    __syncthreads();
}

// ---------------- persistent bidirectional LSTM layer -----------------------
__global__ __launch_bounds__(256, 1) void lstm_kernel(
        const float* __restrict__ Whhf, const float* __restrict__ Whhb,
        int layer) {
    extern __shared__ float smem[];
    float* hs   = smem;                       // [800*32] previous h (both halves of this dir)
    float* pre  = smem + HID*BATCH;           // [44*32] gate pre-activations
    float* csm  = pre + 44*BATCH;             // [11*32] cell state
    float* hout = layer ? g_h1T : g_h0T;

    int bid = blockIdx.x;
    int dir = (bid < 74) ? 0 : 1;
    int lb  = dir ? bid - 74 : bid;           // 0..73
    int nh, h0;
    if (lb < 60) { nh = 11; h0 = lb*11; }
    else         { nh = 10; h0 = 660 + (lb-60)*10; }
    const float* __restrict__ xgT = dir ? g_xgTb : g_xgTf;
    const float* __restrict__ Whh = dir ? Whhb : Whhf;

    int tid = threadIdx.x;
    int lane = tid & 31, w = tid >> 5;
    int nrows = nh * 4;

    // zero-init c (smem) and own rows of h parity-0 buffer
    for (int i = tid; i < nh*BATCH; i += 256) {
        csm[i] = 0.f;
        int hl = i >> 5, b = i & 31;
        g_hstate[((size_t)(dir*2 + 0)*HID + h0 + hl)*BATCH + b] = 0.f;
    }
    grid_barrier();

    for (int t = 0; t < T_SEQ; t++) {
        int te = dir ? (T_SEQ - 1 - t) : t;
        int p = t & 1;
        // stage previous h ([k][b]) into smem; bypass L1 (written by other SMs)
        const float* hsg = &g_hstate[(size_t)(dir*2 + p)*HID*BATCH];
        for (int i = tid; i < HID*BATCH; i += 256) hs[i] = __ldcg(&hsg[i]);
        __syncthreads();

        // phase A: gate pre-activations (two rows per warp iteration)
        for (int lr0 = w; lr0 < nrows; lr0 += 16) {
            int lr1 = lr0 + 8;
            bool v1 = lr1 < nrows;
            int grow0 = (lr0 & 3)*HID + h0 + (lr0 >> 2);
            int grow1 = v1 ? ((lr1 & 3)*HID + h0 + (lr1 >> 2)) : grow0;
            const float* w0p = Whh + (size_t)grow0*HID;
            const float* w1p = Whh + (size_t)grow1*HID;
            float acc0 = xgT[((size_t)te*G4 + grow0)*BATCH + lane];
            float acc1 = v1 ? xgT[((size_t)te*G4 + grow1)*BATCH + lane] : 0.f;
            float a0b = 0.f, a1b = 0.f;
            #pragma unroll 4
            for (int k = 0; k < HID; k += 4) {
                float4 w0v = *(const float4*)(w0p + k);
                float4 w1v = *(const float4*)(w1p + k);
                float hv0 = hs[(k+0)*BATCH + lane];
                float hv1 = hs[(k+1)*BATCH + lane];
                float hv2 = hs[(k+2)*BATCH + lane];
                float hv3 = hs[(k+3)*BATCH + lane];
                acc0 = fmaf(hv0, w0v.x, acc0);  a0b = fmaf(hv1, w0v.y, a0b);
                acc0 = fmaf(hv2, w0v.z, acc0);  a0b = fmaf(hv3, w0v.w, a0b);
                acc1 = fmaf(hv0, w1v.x, acc1);  a1b = fmaf(hv1, w1v.y, a1b);
                acc1 = fmaf(hv2, w1v.z, acc1);  a1b = fmaf(hv3, w1v.w, a1b);
            }
            pre[lr0*BATCH + lane] = acc0 + a0b;
            if (v1) pre[lr1*BATCH + lane] = acc1 + a1b;
        }
        __syncthreads();

        // phase B: gate nonlinearity + state update
        for (int i = tid; i < nh*BATCH; i += 256) {
            int hl = i >> 5, b = i & 31;
            float iv = pre[(hl*4+0)*BATCH + b];
            float fv = pre[(hl*4+1)*BATCH + b];
            float gv = pre[(hl*4+2)*BATCH + b];
            float ov = pre[(hl*4+3)*BATCH + b];
            float si = 1.f/(1.f + expf(-iv));
            float sf = 1.f/(1.f + expf(-fv));
            float so = 1.f/(1.f + expf(-ov));
            float c  = sf*csm[i] + si*tanhf(gv);
            float hv = so*tanhf(c);
            csm[i] = c;
            int hi = h0 + hl;
            g_hstate[((size_t)(dir*2 + (1-p))*HID + hi)*BATCH + b] = hv;
            hout[((size_t)te*L1K + dir*HID + hi)*BATCH + b] = hv;
        }
        grid_barrier();
    }
}

// ---------------- FC + softmax-free angularization -> dihedrals -------------
__global__ __launch_bounds__(256) void fc_dih_kernel(
        const float* __restrict__ fcW, const float* __restrict__ fcb,
        const float* __restrict__ alphabet) {
    __shared__ float chunk[256*BATCH];   // 32KB feature chunk [k][b]
    __shared__ float lsm[NA*BATCH];
    __shared__ float sn[NA*3], cs[NA*3];
    int t = blockIdx.x;
    int tid = threadIdx.x;
    int lane = tid & 31, w = tid >> 5;

    float acc[8];
    #pragma unroll
    for (int i = 0; i < 8; i++) acc[i] = 0.f;

    for (int c0 = 0; c0 < RNNOUT; c0 += 256) {
        int clen = RNNOUT - c0; if (clen > 256) clen = 256;
        for (int idx = tid; idx < clen*BATCH; idx += 256) {
            int k = idx >> 5, b = idx & 31;
            int f = c0 + k;
            chunk[idx] = (f < L1K)
                ? g_h1T[((size_t)t*L1K + f)*BATCH + b]
                : g_xT [((size_t)t*DIN + (f - L1K))*BATCH + b];
        }
        __syncthreads();
        #pragma unroll
        for (int i = 0; i < 8; i++) {
            int a = w*8 + i;
            if (a < NA) {
                const float* wr = fcW + (size_t)a*RNNOUT + c0;
                float s = acc[i];
                #pragma unroll 4
                for (int k = 0; k < clen; k++)
                    s = fmaf(__ldg(wr + k), chunk[k*BATCH + lane], s);
                acc[i] = s;
            }
        }
        __syncthreads();
    }
    #pragma unroll
    for (int i = 0; i < 8; i++) {
        int a = w*8 + i;
        if (a < NA) lsm[a*BATCH + lane] = acc[i] + fcb[a];
    }
    for (int i = tid; i < NA*3; i += 256) {
        float v = alphabet[i];
        sn[i] = sinf(v); cs[i] = cosf(v);
    }
    __syncthreads();
    if (tid < 96) {
        int b = tid & 31, j = tid >> 5;
        float ss = 0.f, cc = 0.f;
        for (int a = 0; a < NA; a++) {
            float e = expf(lsm[a*BATCH + b]);   // softmax Z cancels in atan2
            ss = fmaf(e, sn[a*3 + j], ss);
            cc = fmaf(e, cs[a*3 + j], cc);
        }
        g_dih[((size_t)t*BATCH + b)*3 + j] = atan2f(ss, cc);
    }
}

// ---------------- dihedral -> points -> NeRF coordinate extension -----------
__global__ void geometry_kernel(float* __restrict__ out) {
    int b = threadIdx.x;   // 0..31, one lane per batch element
    const float PI = 3.14159265358979323846f;
    float BL[3] = {145.801f, 152.326f, 132.868f};
    float BA[3] = {2.124f, 1.941f, 2.028f};
    float rct[3], rst[3];
    #pragma unroll
    for (int j = 0; j < 3; j++) {
        rct[j] = BL[j]*cosf(PI - BA[j]);
        rst[j] = BL[j]*sinf(PI - BA[j]);
    }
    float ax = -sqrtf(0.5f), ay = sqrtf(1.5f), az = 0.f;
    float bx = -sqrtf(2.0f), by = 0.f,        bz = 0.f;
    float cx = 0.f, cy = 0.f, cz = 0.f;

    for (int i = 0; i < 3*T_SEQ; i++) {
        int t = i / 3, j = i - 3*t;
        float d  = g_dih[((size_t)t*BATCH + b)*3 + j];
        float p0 = rct[j];
        float p1 = cosf(d)*rst[j];
        float p2 = sinf(d)*rst[j];

        float ux = cx-bx, uy = cy-by, uz = cz-bz;
        float inv = 1.f/sqrtf(ux*ux + uy*uy + uz*uz + 1e-12f);
        float bcx = ux*inv, bcy = uy*inv, bcz = uz*inv;

        float vx = bx-ax, vy = by-ay, vz = bz-az;
        float nx0 = vy*bcz - vz*bcy;
        float ny0 = vz*bcx - vx*bcz;
        float nz0 = vx*bcy - vy*bcx;
        float inv2 = 1.f/sqrtf(nx0*nx0 + ny0*ny0 + nz0*nz0 + 1e-12f);
        float nx = nx0*inv2, ny = ny0*inv2, nz = nz0*inv2;

        float mx = ny*bcz - nz*bcy;
        float my = nz*bcx - nx*bcz;
        float mz = nx*bcy - ny*bcx;

        float ox = cx + p0*bcx + p1*mx + p2*nx;
        float oy = cy + p0*bcy + p1*my + p2*ny;
        float oz = cz + p0*bcz + p1*mz + p2*nz;

        size_t o = ((size_t)i*BATCH + b)*3;
        out[o+0] = ox; out[o+1] = oy; out[o+2] = oz;

        ax = bx; ay = by; az = bz;
        bx = cx; by = cy; bz = cz;
        cx = ox; cy = oy; cz = oz;
    }
}

// ---------------- launch ----------------------------------------------------
extern "C" void kernel_launch(void* const* d_in, const int* in_sizes, int n_in,
                              void* d_out, int out_size) {
    const int*   primary = (const int*)  d_in[0];
    const float* evo     = (const float*)d_in[1];
    // d_in[2] = seq_length (fixed 700, ignored)
    const float* emb     = (const float*)d_in[3];
    const float* Wih0f   = (const float*)d_in[4];
    const float* Whh0f   = (const float*)d_in[5];
    const float* b0f     = (const float*)d_in[6];
    const float* Wih0b   = (const float*)d_in[7];
    const float* Whh0b   = (const float*)d_in[8];
    const float* b0b     = (const float*)d_in[9];
    const float* Wih1f   = (const float*)d_in[10];
    const float* Whh1f   = (const float*)d_in[11];
    const float* b1f     = (const float*)d_in[12];
    const float* Wih1b   = (const float*)d_in[13];
    const float* Whh1b   = (const float*)d_in[14];
    const float* b1b     = (const float*)d_in[15];
    const float* fcW     = (const float*)d_in[16];
    const float* fcb     = (const float*)d_in[17];
    const float* alphabet= (const float*)d_in[18];
    float* out = (float*)d_out;

    cudaFuncSetAttribute(lstm_kernel,
                         cudaFuncAttributeMaxDynamicSharedMemorySize, LSTM_SMEM);

    dim3 ggrid(175, 25);           // 22400/128, 3200/128
    dim3 tgrid(T_SEQ, 100);        // 3200/32
    dim3 tblk(32, 8);

    build_x_kernel<<<T_SEQ, 256>>>(primary, evo, emb);

    // layer 0 input projections
    gemm_tkb_kernel<<<ggrid, 256>>>(Wih0f, b0f, DIN, 0);
    transpose_kernel<<<tgrid, tblk>>>(0);
    gemm_tkb_kernel<<<ggrid, 256>>>(Wih0b, b0b, DIN, 0);
    transpose_kernel<<<tgrid, tblk>>>(1);
    lstm_kernel<<<NB_LSTM, 256, LSTM_SMEM>>>(Whh0f, Whh0b, 0);

    // layer 1 input projections
    gemm_tkb_kernel<<<ggrid, 256>>>(Wih1f, b1f, L1K, 1);
    transpose_kernel<<<tgrid, tblk>>>(0);
    gemm_tkb_kernel<<<ggrid, 256>>>(Wih1b, b1b, L1K, 1);
    transpose_kernel<<<tgrid, tblk>>>(1);
    lstm_kernel<<<NB_LSTM, 256, LSTM_SMEM>>>(Whh1f, Whh1b, 1);

    fc_dih_kernel<<<T_SEQ, 256>>>(fcW, fcb, alphabet);
    geometry_kernel<<<1, 32>>>(out);
}